// round 5
// baseline (speedup 1.0000x reference)
#include <cuda_runtime.h>
#include <cuda_fp16.h>
#include <stdint.h>

#define NSEQ 512
#define SCALE_F 0.04419417382415922f

// Scratch (device globals: allocation-free rule)
__device__ __align__(128) float d_q [16 * 512 * 512];
__device__ __align__(128) float d_k [16 * 512 * 512];
__device__ __align__(128) float d_v [16 * 512 * 1024];
__device__ __align__(128) float d_sc[16 * 8  * 512 * 512];
__device__ __align__(128) float d_aw[16 * 16 * 512 * 512];
__device__ __align__(128) float d_o [16 * 512 * 1024];

__device__ __forceinline__ float tf32r(float x) {
    uint32_t u; asm("cvt.rna.tf32.f32 %0, %1;" : "=r"(u) : "f"(x));
    return __uint_as_float(u);
}
__device__ __forceinline__ void mma8(float* c, const uint32_t* a, const uint32_t* b) {
    asm volatile(
        "mma.sync.aligned.m16n8k8.row.col.f32.tf32.tf32.f32 "
        "{%0,%1,%2,%3}, {%4,%5,%6,%7}, {%8,%9}, {%0,%1,%2,%3};\n"
        : "+f"(c[0]), "+f"(c[1]), "+f"(c[2]), "+f"(c[3])
        : "r"(a[0]), "r"(a[1]), "r"(a[2]), "r"(a[3]), "r"(b[0]), "r"(b[1]));
}

// Generic batched tf32 GEMM: C[M,N] = A[M,K] @ B  (+bias[col])
// transB=0: B is [K,N] row-major; transB=1: B is [N,K] row-major (B^T).
// Batch z = blockIdx.y; b = z>>innerShift, j = z & mask; offsets linear in (b,j).
__global__ __launch_bounds__(256) void gemm_tf32(
    const float* __restrict__ A, const float* __restrict__ B,
    float* __restrict__ C, const float* __restrict__ bias,
    int M, int N, int K, int lda, int ldb, int ldc, int transB,
    int innerShift, long sAb, long sAj, long sBb, long sBj, long sCb, long sCj)
{
    __shared__ __align__(16) float As[128][36];
    __shared__ __align__(16) float Bs[64][36];

    const int tid = threadIdx.x;
    const int tilesN = N >> 6;
    const int tm = blockIdx.x / tilesN, tn = blockIdx.x % tilesN;
    const int row0 = tm * 128, col0 = tn * 64;

    const int z = blockIdx.y;
    const int bb = z >> innerShift, jj = z & ((1 << innerShift) - 1);
    const float* Ab = A + bb * sAb + jj * sAj;
    const float* Bb = B + bb * sBb + jj * sBj;
    float*       Cb = C + bb * sCb + jj * sCj;

    const int lane = tid & 31, wid = tid >> 5;
    const int wm = wid & 3, wn = wid >> 2;      // 4 (M) x 2 (N) warps
    const int g = lane >> 2, t = lane & 3;

    float c[2][4][4];
    #pragma unroll
    for (int mi = 0; mi < 2; mi++)
        #pragma unroll
        for (int ni = 0; ni < 4; ni++)
            #pragma unroll
            for (int ci = 0; ci < 4; ci++) c[mi][ni][ci] = 0.0f;

    for (int k0 = 0; k0 < K; k0 += 32) {
        // A tile: 128 x 32
        #pragma unroll
        for (int i = 0; i < 4; i++) {
            int f = tid + i * 256;
            int r = f >> 3, c4 = (f & 7) * 4;
            float4 v4 = *(const float4*)(Ab + (size_t)(row0 + r) * lda + k0 + c4);
            float4 cv = make_float4(tf32r(v4.x), tf32r(v4.y), tf32r(v4.z), tf32r(v4.w));
            *(float4*)&As[r][c4] = cv;
        }
        // B tile -> Bs[n'][kk]
        if (transB) {
            #pragma unroll
            for (int i = 0; i < 2; i++) {
                int f = tid + i * 256;
                int r = f >> 3, c4 = (f & 7) * 4;   // r: n' 0..63, c4: k
                float4 v4 = *(const float4*)(Bb + (size_t)(col0 + r) * ldb + k0 + c4);
                float4 cv = make_float4(tf32r(v4.x), tf32r(v4.y), tf32r(v4.z), tf32r(v4.w));
                *(float4*)&Bs[r][c4] = cv;
            }
        } else {
            #pragma unroll
            for (int i = 0; i < 2; i++) {
                int f = tid + i * 256;
                int kk = f >> 4, n4 = (f & 15) * 4;
                float4 v4 = *(const float4*)(Bb + (size_t)(k0 + kk) * ldb + col0 + n4);
                Bs[n4 + 0][kk] = tf32r(v4.x);
                Bs[n4 + 1][kk] = tf32r(v4.y);
                Bs[n4 + 2][kk] = tf32r(v4.z);
                Bs[n4 + 3][kk] = tf32r(v4.w);
            }
        }
        __syncthreads();
        #pragma unroll
        for (int ks = 0; ks < 4; ks++) {
            int kb = ks * 8;
            uint32_t af[2][4], bf[4][2];
            #pragma unroll
            for (int mi = 0; mi < 2; mi++) {
                int rb = wm * 32 + mi * 16 + g;
                af[mi][0] = __float_as_uint(As[rb][kb + t]);
                af[mi][1] = __float_as_uint(As[rb + 8][kb + t]);
                af[mi][2] = __float_as_uint(As[rb][kb + t + 4]);
                af[mi][3] = __float_as_uint(As[rb + 8][kb + t + 4]);
            }
            #pragma unroll
            for (int ni = 0; ni < 4; ni++) {
                int cb = wn * 32 + ni * 8 + g;
                bf[ni][0] = __float_as_uint(Bs[cb][kb + t]);
                bf[ni][1] = __float_as_uint(Bs[cb][kb + t + 4]);
            }
            #pragma unroll
            for (int mi = 0; mi < 2; mi++)
                #pragma unroll
                for (int ni = 0; ni < 4; ni++)
                    mma8(c[mi][ni], af[mi], bf[ni]);
        }
        __syncthreads();
    }

    #pragma unroll
    for (int mi = 0; mi < 2; mi++)
        #pragma unroll
        for (int ni = 0; ni < 4; ni++)
            #pragma unroll
            for (int ci = 0; ci < 4; ci++) {
                int row = row0 + wm * 32 + mi * 16 + g + ((ci & 2) ? 8 : 0);
                int col = col0 + wn * 32 + ni * 8 + 2 * t + (ci & 1);
                float val = c[mi][ni][ci];
                if (bias) val += bias[col];
                Cb[(size_t)row * ldc + col] = val;
            }
}

__device__ __forceinline__ float mish_f(float x) {
    float sp = (x > 20.0f) ? x : log1pf(__expf(x));
    return x * tanhf(sp);
}

// Fused: noise + head-mix MLP (mish) + prior + softmax over L -> d_aw
__global__ __launch_bounds__(256) void k_mid(
    const float* __restrict__ prior, const float* __restrict__ eps,
    const float* __restrict__ sigma,
    const float* __restrict__ Wp1, const float* __restrict__ bp1,
    const float* __restrict__ Wp2, const float* __restrict__ bp2)
{
    __shared__ float sW1[128], sW2[256], sb1[16], sb2[16], ss2[8];
    const int tid = threadIdx.x;
    if (tid < 128) sW1[tid] = Wp1[tid];
    sW2[tid] = Wp2[tid];
    if (tid < 16) { sb1[tid] = bp1[tid]; sb2[tid] = bp2[tid]; }
    if (tid < 8)  { float s = sigma[tid]; ss2[tid] = s * s; }
    __syncthreads();

    const size_t pos = (size_t)blockIdx.x * 256 + tid;   // b*N*N + n*N + m
    const int m = (int)(pos & 511);
    const int n = (int)((pos >> 9) & 511);
    const int b = (int)(pos >> 18);

    float s[8];
    bool pad = true;
    #pragma unroll
    for (int gi = 0; gi < 8; gi++) {
        s[gi] = d_sc[((size_t)(b * 8 + gi) * 512 + n) * 512 + m];
        pad = pad && (s[gi] == 0.0f);
    }
    const float4* ep = (const float4*)(eps + ((size_t)(b * 512 + n) * 512 + m) * 8);
    float4 e0 = ep[0], e1 = ep[1];
    float av[8];
    av[0] = s[0] + ss2[0] * e0.x; av[1] = s[1] + ss2[1] * e0.y;
    av[2] = s[2] + ss2[2] * e0.z; av[3] = s[3] + ss2[3] * e0.w;
    av[4] = s[4] + ss2[4] * e1.x; av[5] = s[5] + ss2[5] * e1.y;
    av[6] = s[6] + ss2[6] * e1.z; av[7] = s[7] + ss2[7] * e1.w;

    float h[16];
    #pragma unroll
    for (int l = 0; l < 16; l++) {
        float acc = sb1[l];
        #pragma unroll
        for (int gi = 0; gi < 8; gi++) acc += av[gi] * sW1[gi * 16 + l];
        h[l] = mish_f(acc);
    }
    float f[16], mx = -1e30f;
    #pragma unroll
    for (int l = 0; l < 16; l++) {
        float acc = sb2[l];
        #pragma unroll
        for (int j = 0; j < 16; j++) acc += h[j] * sW2[j * 16 + l];
        float logit = acc * SCALE_F + prior[((size_t)(b * 16 + l) * 512 + n) * 512 + m];
        f[l] = logit;
        mx = fmaxf(mx, logit);
    }
    float sum = 0.0f;
    #pragma unroll
    for (int l = 0; l < 16; l++) { f[l] = __expf(f[l] - mx); sum += f[l]; }
    float inv = pad ? 0.0f : (1.0f / sum);
    #pragma unroll
    for (int l = 0; l < 16; l++)
        d_aw[((size_t)(b * 16 + l) * 512 + n) * 512 + m] = f[l] * inv;
}

extern "C" void kernel_launch(void* const* d_in, const int* in_sizes, int n_in,
                              void* d_out, int out_size)
{
    const float* x     = (const float*)d_in[0];
    const float* prior = (const float*)d_in[1];
    const float* eps   = (const float*)d_in[2];
    const float* Wq    = (const float*)d_in[3];
    const float* Wk    = (const float*)d_in[4];
    const float* Wv    = (const float*)d_in[5];
    const float* bv    = (const float*)d_in[6];
    const float* sigma = (const float*)d_in[7];
    const float* Wp1   = (const float*)d_in[8];
    const float* bp1   = (const float*)d_in[9];
    const float* Wp2   = (const float*)d_in[10];
    const float* bp2   = (const float*)d_in[11];
    const float* Wout  = (const float*)d_in[12];
    float* out = (float*)d_out;

    float *q, *k, *v, *sc, *aw, *o;
    cudaGetSymbolAddress((void**)&q,  d_q);
    cudaGetSymbolAddress((void**)&k,  d_k);
    cudaGetSymbolAddress((void**)&v,  d_v);
    cudaGetSymbolAddress((void**)&sc, d_sc);
    cudaGetSymbolAddress((void**)&aw, d_aw);
    cudaGetSymbolAddress((void**)&o,  d_o);

    const long S = 512L * 512L;   // 262144

    // q = x @ Wq   (8192x512x512)
    gemm_tf32<<<dim3(64 * 8, 1), 256>>>(x, Wq, q, nullptr,
        8192, 512, 512, 512, 512, 512, 0, 0, 0,0,0,0,0,0);
    // k = x @ Wk
    gemm_tf32<<<dim3(64 * 8, 1), 256>>>(x, Wk, k, nullptr,
        8192, 512, 512, 512, 512, 512, 0, 0, 0,0,0,0,0,0);
    // v = x @ Wv + bv  (8192x1024)
    gemm_tf32<<<dim3(64 * 16, 1), 256>>>(x, Wv, v, bv,
        8192, 1024, 512, 512, 1024, 1024, 0, 0, 0,0,0,0,0,0);
    // scores[b,g] = q_g @ k_g^T   batch 128
    gemm_tf32<<<dim3(4 * 8, 128), 256>>>(q, k, sc, nullptr,
        512, 512, 64, 512, 512, 512, 1,
        3, S, 64, S, 64, 8 * S, S);
    // mid: noise + MLP + prior + softmax(L)
    k_mid<<<16384, 256>>>(prior, eps, sigma, Wp1, bp1, Wp2, bp2);
    // o[b,:,l,:] = aw[b,l] @ v[b,:,l,:]   batch 256
    gemm_tf32<<<dim3(4 * 1, 256), 256>>>(aw, v, o, nullptr,
        512, 64, 512, 512, 1024, 1024, 0,
        4, 16 * S, S, 2 * S, 64, 2 * S, 64);
    // out = o @ Wout  (8192x1024 @ 1024x512)
    gemm_tf32<<<dim3(64 * 8, 1), 256>>>(o, Wout, out, nullptr,
        8192, 512, 1024, 1024, 512, 512, 0, 0, 0,0,0,0,0,0);
}

// round 6
// speedup vs baseline: 1.0076x; 1.0076x over previous
#include <cuda_runtime.h>
#include <cuda_fp16.h>
#include <stdint.h>

#define NSEQ 512
#define SCALE_F 0.04419417382415922f

// Scratch (device globals: allocation-free rule)
__device__ __align__(128) float d_q [16 * 512 * 512];
__device__ __align__(128) float d_k [16 * 512 * 512];
__device__ __align__(128) float d_v [16 * 512 * 1024];
__device__ __align__(128) float d_sc[16 * 8  * 512 * 512];
__device__ __align__(128) float d_aw[16 * 16 * 512 * 512];
__device__ __align__(128) float d_o [16 * 512 * 1024];

__device__ __forceinline__ float tf32r(float x) {
    uint32_t u; asm("cvt.rna.tf32.f32 %0, %1;" : "=r"(u) : "f"(x));
    return __uint_as_float(u);
}
__device__ __forceinline__ void mma8(float* c, const uint32_t* a, const uint32_t* b) {
    asm volatile(
        "mma.sync.aligned.m16n8k8.row.col.f32.tf32.tf32.f32 "
        "{%0,%1,%2,%3}, {%4,%5,%6,%7}, {%8,%9}, {%0,%1,%2,%3};\n"
        : "+f"(c[0]), "+f"(c[1]), "+f"(c[2]), "+f"(c[3])
        : "r"(a[0]), "r"(a[1]), "r"(a[2]), "r"(a[3]), "r"(b[0]), "r"(b[1]));
}

// Generic batched tf32 GEMM: C[M,N] = A[M,K] @ B  (+bias[col])
// transB=0: B is [K,N] row-major; transB=1: B is [N,K] row-major (B^T).
// Batch z = blockIdx.y; b = z>>innerShift, j = z & mask; offsets linear in (b,j).
__global__ __launch_bounds__(256) void gemm_tf32(
    const float* __restrict__ A, const float* __restrict__ B,
    float* __restrict__ C, const float* __restrict__ bias,
    int M, int N, int K, int lda, int ldb, int ldc, int transB,
    int innerShift, long sAb, long sAj, long sBb, long sBj, long sCb, long sCj)
{
    __shared__ __align__(16) float As[128][36];
    __shared__ __align__(16) float Bs[64][36];

    const int tid = threadIdx.x;
    const int tilesN = N >> 6;
    const int tm = blockIdx.x / tilesN, tn = blockIdx.x % tilesN;
    const int row0 = tm * 128, col0 = tn * 64;

    const int z = blockIdx.y;
    const int bb = z >> innerShift, jj = z & ((1 << innerShift) - 1);
    const float* Ab = A + bb * sAb + jj * sAj;
    const float* Bb = B + bb * sBb + jj * sBj;
    float*       Cb = C + bb * sCb + jj * sCj;

    const int lane = tid & 31, wid = tid >> 5;
    const int wm = wid & 3, wn = wid >> 2;      // 4 (M) x 2 (N) warps
    const int g = lane >> 2, t = lane & 3;

    float c[2][4][4];
    #pragma unroll
    for (int mi = 0; mi < 2; mi++)
        #pragma unroll
        for (int ni = 0; ni < 4; ni++)
            #pragma unroll
            for (int ci = 0; ci < 4; ci++) c[mi][ni][ci] = 0.0f;

    for (int k0 = 0; k0 < K; k0 += 32) {
        // A tile: 128 x 32
        #pragma unroll
        for (int i = 0; i < 4; i++) {
            int f = tid + i * 256;
            int r = f >> 3, c4 = (f & 7) * 4;
            float4 v4 = *(const float4*)(Ab + (size_t)(row0 + r) * lda + k0 + c4);
            float4 cv = make_float4(tf32r(v4.x), tf32r(v4.y), tf32r(v4.z), tf32r(v4.w));
            *(float4*)&As[r][c4] = cv;
        }
        // B tile -> Bs[n'][kk]
        if (transB) {
            #pragma unroll
            for (int i = 0; i < 2; i++) {
                int f = tid + i * 256;
                int r = f >> 3, c4 = (f & 7) * 4;   // r: n' 0..63, c4: k
                float4 v4 = *(const float4*)(Bb + (size_t)(col0 + r) * ldb + k0 + c4);
                float4 cv = make_float4(tf32r(v4.x), tf32r(v4.y), tf32r(v4.z), tf32r(v4.w));
                *(float4*)&Bs[r][c4] = cv;
            }
        } else {
            #pragma unroll
            for (int i = 0; i < 2; i++) {
                int f = tid + i * 256;
                int kk = f >> 4, n4 = (f & 15) * 4;
                float4 v4 = *(const float4*)(Bb + (size_t)(k0 + kk) * ldb + col0 + n4);
                Bs[n4 + 0][kk] = tf32r(v4.x);
                Bs[n4 + 1][kk] = tf32r(v4.y);
                Bs[n4 + 2][kk] = tf32r(v4.z);
                Bs[n4 + 3][kk] = tf32r(v4.w);
            }
        }
        __syncthreads();
        #pragma unroll
        for (int ks = 0; ks < 4; ks++) {
            int kb = ks * 8;
            uint32_t af[2][4], bf[4][2];
            #pragma unroll
            for (int mi = 0; mi < 2; mi++) {
                int rb = wm * 32 + mi * 16 + g;
                af[mi][0] = __float_as_uint(As[rb][kb + t]);
                af[mi][1] = __float_as_uint(As[rb + 8][kb + t]);
                af[mi][2] = __float_as_uint(As[rb][kb + t + 4]);
                af[mi][3] = __float_as_uint(As[rb + 8][kb + t + 4]);
            }
            #pragma unroll
            for (int ni = 0; ni < 4; ni++) {
                int cb = wn * 32 + ni * 8 + g;
                bf[ni][0] = __float_as_uint(Bs[cb][kb + t]);
                bf[ni][1] = __float_as_uint(Bs[cb][kb + t + 4]);
            }
            #pragma unroll
            for (int mi = 0; mi < 2; mi++)
                #pragma unroll
                for (int ni = 0; ni < 4; ni++)
                    mma8(c[mi][ni], af[mi], bf[ni]);
        }
        __syncthreads();
    }

    #pragma unroll
    for (int mi = 0; mi < 2; mi++)
        #pragma unroll
        for (int ni = 0; ni < 4; ni++)
            #pragma unroll
            for (int ci = 0; ci < 4; ci++) {
                int row = row0 + wm * 32 + mi * 16 + g + ((ci & 2) ? 8 : 0);
                int col = col0 + wn * 32 + ni * 8 + 2 * t + (ci & 1);
                float val = c[mi][ni][ci];
                if (bias) val += bias[col];
                Cb[(size_t)row * ldc + col] = val;
            }
}

__device__ __forceinline__ float mish_f(float x) {
    float sp = (x > 20.0f) ? x : log1pf(__expf(x));
    return x * tanhf(sp);
}

// Fused: noise + head-mix MLP (mish) + prior + softmax over L -> d_aw
__global__ __launch_bounds__(256) void k_mid(
    const float* __restrict__ prior, const float* __restrict__ eps,
    const float* __restrict__ sigma,
    const float* __restrict__ Wp1, const float* __restrict__ bp1,
    const float* __restrict__ Wp2, const float* __restrict__ bp2)
{
    __shared__ float sW1[128], sW2[256], sb1[16], sb2[16], ss2[8];
    const int tid = threadIdx.x;
    if (tid < 128) sW1[tid] = Wp1[tid];
    sW2[tid] = Wp2[tid];
    if (tid < 16) { sb1[tid] = bp1[tid]; sb2[tid] = bp2[tid]; }
    if (tid < 8)  { float s = sigma[tid]; ss2[tid] = s * s; }
    __syncthreads();

    const size_t pos = (size_t)blockIdx.x * 256 + tid;   // b*N*N + n*N + m
    const int m = (int)(pos & 511);
    const int n = (int)((pos >> 9) & 511);
    const int b = (int)(pos >> 18);

    float s[8];
    bool pad = true;
    #pragma unroll
    for (int gi = 0; gi < 8; gi++) {
        s[gi] = d_sc[((size_t)(b * 8 + gi) * 512 + n) * 512 + m];
        pad = pad && (s[gi] == 0.0f);
    }
    const float4* ep = (const float4*)(eps + ((size_t)(b * 512 + n) * 512 + m) * 8);
    float4 e0 = ep[0], e1 = ep[1];
    float av[8];
    av[0] = s[0] + ss2[0] * e0.x; av[1] = s[1] + ss2[1] * e0.y;
    av[2] = s[2] + ss2[2] * e0.z; av[3] = s[3] + ss2[3] * e0.w;
    av[4] = s[4] + ss2[4] * e1.x; av[5] = s[5] + ss2[5] * e1.y;
    av[6] = s[6] + ss2[6] * e1.z; av[7] = s[7] + ss2[7] * e1.w;

    float h[16];
    #pragma unroll
    for (int l = 0; l < 16; l++) {
        float acc = sb1[l];
        #pragma unroll
        for (int gi = 0; gi < 8; gi++) acc += av[gi] * sW1[gi * 16 + l];
        h[l] = mish_f(acc);
    }
    float f[16], mx = -1e30f;
    #pragma unroll
    for (int l = 0; l < 16; l++) {
        float acc = sb2[l];
        #pragma unroll
        for (int j = 0; j < 16; j++) acc += h[j] * sW2[j * 16 + l];
        float logit = acc * SCALE_F + prior[((size_t)(b * 16 + l) * 512 + n) * 512 + m];
        f[l] = logit;
        mx = fmaxf(mx, logit);
    }
    float sum = 0.0f;
    #pragma unroll
    for (int l = 0; l < 16; l++) { f[l] = __expf(f[l] - mx); sum += f[l]; }
    float inv = pad ? 0.0f : (1.0f / sum);
    #pragma unroll
    for (int l = 0; l < 16; l++)
        d_aw[((size_t)(b * 16 + l) * 512 + n) * 512 + m] = f[l] * inv;
}

extern "C" void kernel_launch(void* const* d_in, const int* in_sizes, int n_in,
                              void* d_out, int out_size)
{
    const float* x     = (const float*)d_in[0];
    const float* prior = (const float*)d_in[1];
    const float* eps   = (const float*)d_in[2];
    const float* Wq    = (const float*)d_in[3];
    const float* Wk    = (const float*)d_in[4];
    const float* Wv    = (const float*)d_in[5];
    const float* bv    = (const float*)d_in[6];
    const float* sigma = (const float*)d_in[7];
    const float* Wp1   = (const float*)d_in[8];
    const float* bp1   = (const float*)d_in[9];
    const float* Wp2   = (const float*)d_in[10];
    const float* bp2   = (const float*)d_in[11];
    const float* Wout  = (const float*)d_in[12];
    float* out = (float*)d_out;

    float *q, *k, *v, *sc, *aw, *o;
    cudaGetSymbolAddress((void**)&q,  d_q);
    cudaGetSymbolAddress((void**)&k,  d_k);
    cudaGetSymbolAddress((void**)&v,  d_v);
    cudaGetSymbolAddress((void**)&sc, d_sc);
    cudaGetSymbolAddress((void**)&aw, d_aw);
    cudaGetSymbolAddress((void**)&o,  d_o);

    const long S = 512L * 512L;   // 262144

    // q = x @ Wq   (8192x512x512)
    gemm_tf32<<<dim3(64 * 8, 1), 256>>>(x, Wq, q, nullptr,
        8192, 512, 512, 512, 512, 512, 0, 0, 0,0,0,0,0,0);
    // k = x @ Wk
    gemm_tf32<<<dim3(64 * 8, 1), 256>>>(x, Wk, k, nullptr,
        8192, 512, 512, 512, 512, 512, 0, 0, 0,0,0,0,0,0);
    // v = x @ Wv + bv  (8192x1024)
    gemm_tf32<<<dim3(64 * 16, 1), 256>>>(x, Wv, v, bv,
        8192, 1024, 512, 512, 1024, 1024, 0, 0, 0,0,0,0,0,0);
    // scores[b,g] = q_g @ k_g^T   batch 128
    gemm_tf32<<<dim3(4 * 8, 128), 256>>>(q, k, sc, nullptr,
        512, 512, 64, 512, 512, 512, 1,
        3, S, 64, S, 64, 8 * S, S);
    // mid: noise + MLP + prior + softmax(L)
    k_mid<<<16384, 256>>>(prior, eps, sigma, Wp1, bp1, Wp2, bp2);
    // o[b,:,l,:] = aw[b,l] @ v[b,:,l,:]   batch 256
    gemm_tf32<<<dim3(4 * 1, 256), 256>>>(aw, v, o, nullptr,
        512, 64, 512, 512, 1024, 1024, 0,
        4, 16 * S, S, 2 * S, 64, 2 * S, 64);
    // out = o @ Wout  (8192x1024 @ 1024x512)
    gemm_tf32<<<dim3(64 * 8, 1), 256>>>(o, Wout, out, nullptr,
        8192, 512, 1024, 1024, 512, 512, 0, 0, 0,0,0,0,0,0);
}

// round 7
// speedup vs baseline: 1.8163x; 1.8026x over previous
#include <cuda_runtime.h>
#include <cuda_fp16.h>
#include <stdint.h>

#define NSEQ 512
#define SCALE_F 0.04419417382415922f

// ---------------------------------------------------------------------------
// Scratch (device globals: allocation-free rule)
// ---------------------------------------------------------------------------
__device__ __align__(128) __half d_qkv [16L * 512 * 2048];        // [b][n][2048]: q|k|v
__device__ __align__(128) __half d_sc  [16L * 8  * 512 * 512];    // [b][g][n][m]
__device__ __align__(128) __half d_aw  [16L * 16 * 512 * 512];    // [b][l][n][m]
__device__ __align__(128) __half d_o   [16L * 512 * 1024];        // [b][n][l*64+d]
__device__ __align__(128) __half d_wqkv[512 * 2048];              // [k][n] n-major
__device__ __align__(128) __half d_wouth[1024 * 512];             // [k][n] n-major
__device__ __align__(128) float  d_bqkv[2048];                    // 0 | 0 | bv

// ---------------------------------------------------------------------------
__device__ __forceinline__ void mma16(float* c, const uint32_t* a, const uint32_t* b) {
    asm volatile(
        "mma.sync.aligned.m16n8k16.row.col.f32.f16.f16.f32 "
        "{%0,%1,%2,%3}, {%4,%5,%6,%7}, {%8,%9}, {%0,%1,%2,%3};\n"
        : "+f"(c[0]), "+f"(c[1]), "+f"(c[2]), "+f"(c[3])
        : "r"(a[0]), "r"(a[1]), "r"(a[2]), "r"(a[3]), "r"(b[0]), "r"(b[1]));
}

// Generic batched fp16 GEMM, fp32 accumulate.  C[M,N] = A[M,K] @ B (+bias[col])
// AH: 1 = A is half, 0 = A is float (converted while staging)
// TB: 1 = B stored [N][K] row-major (K-major, "B^T"), 0 = B stored [K][N] row-major
// OH: 1 = C stored half, 0 = C stored float
// Tile: 128x64, kc=64, 8 warps (4 M x 2 N), warp tile 32x32.
template<int AH, int TB, int OH>
__global__ __launch_bounds__(256) void gemm_h(
    const void* __restrict__ Av, const __half* __restrict__ B,
    void* __restrict__ Cv, const float* __restrict__ bias,
    int M, int N, int K, int lda, int ldb, int ldc,
    int innerShift, long sAb, long sAj, long sBb, long sBj, long sCb, long sCj)
{
    __shared__ __align__(16) __half As[128][72];
    __shared__ __align__(16) __half Bs[64][72];

    const int tid = threadIdx.x;
    const int tilesN = N >> 6;
    const int tm = blockIdx.x / tilesN, tn = blockIdx.x % tilesN;
    const int row0 = tm * 128, col0 = tn * 64;

    const int z = blockIdx.y;
    const int bb = z >> innerShift, jj = z & ((1 << innerShift) - 1);
    const float*  Af = (const float*)Av  + bb * sAb + jj * sAj;
    const __half* Ah = (const __half*)Av + bb * sAb + jj * sAj;
    const __half* Bb = B + bb * sBb + jj * sBj;

    const int lane = tid & 31, wid = tid >> 5;
    const int wm = wid & 3, wn = wid >> 2;
    const int g = lane >> 2, t = lane & 3;

    float c[2][4][4];
    #pragma unroll
    for (int mi = 0; mi < 2; mi++)
        #pragma unroll
        for (int ni = 0; ni < 4; ni++)
            #pragma unroll
            for (int ci = 0; ci < 4; ci++) c[mi][ni][ci] = 0.0f;

    for (int k0 = 0; k0 < K; k0 += 64) {
        // ---- stage A: 128 x 64 halves ----
        #pragma unroll
        for (int i = 0; i < 4; i++) {
            int f = tid + i * 256;
            int r = f >> 3, c8 = (f & 7) * 8;
            if (AH) {
                uint4 u = *(const uint4*)(Ah + (size_t)(row0 + r) * lda + k0 + c8);
                *(uint4*)&As[r][c8] = u;
            } else {
                const float4* p = (const float4*)(Af + (size_t)(row0 + r) * lda + k0 + c8);
                float4 u0 = p[0], u1 = p[1];
                __half h8[8];
                h8[0] = __float2half(u0.x); h8[1] = __float2half(u0.y);
                h8[2] = __float2half(u0.z); h8[3] = __float2half(u0.w);
                h8[4] = __float2half(u1.x); h8[5] = __float2half(u1.y);
                h8[6] = __float2half(u1.z); h8[7] = __float2half(u1.w);
                *(uint4*)&As[r][c8] = *(uint4*)h8;
            }
        }
        // ---- stage B: 64 x 64 halves -> Bs[n][k] ----
        if (TB) {
            #pragma unroll
            for (int i = 0; i < 2; i++) {
                int f = tid + i * 256;
                int r = f >> 3, c8 = (f & 7) * 8;
                uint4 u = *(const uint4*)(Bb + (size_t)(col0 + r) * ldb + k0 + c8);
                *(uint4*)&Bs[r][c8] = u;
            }
        } else {
            #pragma unroll
            for (int it2 = 0; it2 < 2; it2++) {
                int n = tid & 63;
                int kg = ((tid >> 6) << 3) + it2 * 32;
                __half h8[8];
                #pragma unroll
                for (int j = 0; j < 8; j++)
                    h8[j] = Bb[(size_t)(k0 + kg + j) * ldb + col0 + n];
                *(uint4*)&Bs[n][kg] = *(uint4*)h8;
            }
        }
        __syncthreads();
        // ---- mainloop: 4 k16 steps ----
        #pragma unroll
        for (int ks = 0; ks < 4; ks++) {
            int kb = ks * 16;
            uint32_t af[2][4], bf[4][2];
            #pragma unroll
            for (int mi = 0; mi < 2; mi++) {
                int rb = wm * 32 + mi * 16 + g;
                af[mi][0] = *(const uint32_t*)&As[rb    ][kb + 2 * t];
                af[mi][1] = *(const uint32_t*)&As[rb + 8][kb + 2 * t];
                af[mi][2] = *(const uint32_t*)&As[rb    ][kb + 2 * t + 8];
                af[mi][3] = *(const uint32_t*)&As[rb + 8][kb + 2 * t + 8];
            }
            #pragma unroll
            for (int ni = 0; ni < 4; ni++) {
                int cb = wn * 32 + ni * 8 + g;
                bf[ni][0] = *(const uint32_t*)&Bs[cb][kb + 2 * t];
                bf[ni][1] = *(const uint32_t*)&Bs[cb][kb + 2 * t + 8];
            }
            #pragma unroll
            for (int mi = 0; mi < 2; mi++)
                #pragma unroll
                for (int ni = 0; ni < 4; ni++)
                    mma16(c[mi][ni], af[mi], bf[ni]);
        }
        __syncthreads();
    }

    // ---- epilogue ----
    #pragma unroll
    for (int mi = 0; mi < 2; mi++)
        #pragma unroll
        for (int ni = 0; ni < 4; ni++) {
            int row = row0 + wm * 32 + mi * 16 + g;
            int col = col0 + wn * 32 + ni * 8 + 2 * t;
            float b0f = 0.0f, b1f = 0.0f;
            if (bias) { b0f = bias[col]; b1f = bias[col + 1]; }
            float v0 = c[mi][ni][0] + b0f, v1 = c[mi][ni][1] + b1f;
            float v2 = c[mi][ni][2] + b0f, v3 = c[mi][ni][3] + b1f;
            if (OH) {
                __half* Ch = (__half*)Cv + bb * sCb + jj * sCj;
                *(__half2*)(Ch + (size_t)row * ldc + col)       = __floats2half2_rn(v0, v1);
                *(__half2*)(Ch + (size_t)(row + 8) * ldc + col) = __floats2half2_rn(v2, v3);
            } else {
                float* Cf = (float*)Cv + bb * sCb + jj * sCj;
                *(float2*)(Cf + (size_t)row * ldc + col)       = make_float2(v0, v1);
                *(float2*)(Cf + (size_t)(row + 8) * ldc + col) = make_float2(v2, v3);
            }
        }
}

// ---------------------------------------------------------------------------
// Weight prepack: fp32 -> fp16, fuse Wq|Wk|Wv, zero-padded bias
// ---------------------------------------------------------------------------
__global__ __launch_bounds__(256) void prepack(
    const float* __restrict__ Wq, const float* __restrict__ Wk,
    const float* __restrict__ Wv, const float* __restrict__ bv,
    const float* __restrict__ Wout)
{
    int idx = blockIdx.x * 256 + threadIdx.x;       // 0 .. 1048575
    {
        int k = idx >> 11, c = idx & 2047;
        float val;
        if (c < 512)       val = Wq[k * 512 + c];
        else if (c < 1024) val = Wk[k * 512 + (c - 512)];
        else               val = Wv[k * 1024 + (c - 1024)];
        d_wqkv[idx] = __float2half(val);
    }
    if (idx < 1024 * 512) d_wouth[idx] = __float2half(Wout[idx]);
    if (idx < 2048)       d_bqkv[idx] = (idx < 1024) ? 0.0f : bv[idx - 1024];
}

// ---------------------------------------------------------------------------
// mish(x) = x * (u^2+2u)/(u^2+2u+2), u = e^x   (exact identity)
// ---------------------------------------------------------------------------
__device__ __forceinline__ float mish_f(float x) {
    if (x > 30.0f) return x;
    float u = __expf(x);
    float w = u * u + 2.0f * u;
    return x * w * (1.0f / (w + 2.0f));
}

// Fused: noise + head-mix MLP (mish) + prior + softmax over L -> d_aw (half)
__global__ __launch_bounds__(256) void k_mid(
    const float* __restrict__ prior, const float* __restrict__ eps,
    const float* __restrict__ sigma,
    const float* __restrict__ Wp1, const float* __restrict__ bp1,
    const float* __restrict__ Wp2, const float* __restrict__ bp2)
{
    __shared__ float sW1[128], sW2[256], sb1[16], sb2[16], ss2[8];
    const int tid = threadIdx.x;
    if (tid < 128) sW1[tid] = Wp1[tid];
    sW2[tid] = Wp2[tid];
    if (tid < 16) { sb1[tid] = bp1[tid]; sb2[tid] = bp2[tid]; }
    if (tid < 8)  { float s = sigma[tid]; ss2[tid] = s * s; }
    __syncthreads();

    const size_t pos = (size_t)blockIdx.x * 256 + tid;   // b*N*N + n*N + m
    const int m = (int)(pos & 511);
    const int n = (int)((pos >> 9) & 511);
    const int b = (int)(pos >> 18);

    float s[8];
    bool pad = true;
    #pragma unroll
    for (int gi = 0; gi < 8; gi++) {
        s[gi] = __half2float(d_sc[((size_t)(b * 8 + gi) * 512 + n) * 512 + m]);
        pad = pad && (s[gi] == 0.0f);
    }
    const float4* ep = (const float4*)(eps + ((size_t)(b * 512 + n) * 512 + m) * 8);
    float4 e0 = ep[0], e1 = ep[1];
    float av[8];
    av[0] = s[0] + ss2[0] * e0.x; av[1] = s[1] + ss2[1] * e0.y;
    av[2] = s[2] + ss2[2] * e0.z; av[3] = s[3] + ss2[3] * e0.w;
    av[4] = s[4] + ss2[4] * e1.x; av[5] = s[5] + ss2[5] * e1.y;
    av[6] = s[6] + ss2[6] * e1.z; av[7] = s[7] + ss2[7] * e1.w;

    float h[16];
    #pragma unroll
    for (int l = 0; l < 16; l++) {
        float acc = sb1[l];
        #pragma unroll
        for (int gi = 0; gi < 8; gi++) acc += av[gi] * sW1[gi * 16 + l];
        h[l] = mish_f(acc);
    }
    float f[16], mx = -1e30f;
    #pragma unroll
    for (int l = 0; l < 16; l++) {
        float acc = sb2[l];
        #pragma unroll
        for (int j = 0; j < 16; j++) acc += h[j] * sW2[j * 16 + l];
        float logit = acc * SCALE_F + prior[((size_t)(b * 16 + l) * 512 + n) * 512 + m];
        f[l] = logit;
        mx = fmaxf(mx, logit);
    }
    float sum = 0.0f;
    #pragma unroll
    for (int l = 0; l < 16; l++) { f[l] = __expf(f[l] - mx); sum += f[l]; }
    float inv = pad ? 0.0f : (1.0f / sum);
    #pragma unroll
    for (int l = 0; l < 16; l++)
        d_aw[((size_t)(b * 16 + l) * 512 + n) * 512 + m] = __float2half(f[l] * inv);
}

// ---------------------------------------------------------------------------
extern "C" void kernel_launch(void* const* d_in, const int* in_sizes, int n_in,
                              void* d_out, int out_size)
{
    const float* x     = (const float*)d_in[0];
    const float* prior = (const float*)d_in[1];
    const float* eps   = (const float*)d_in[2];
    const float* Wq    = (const float*)d_in[3];
    const float* Wk    = (const float*)d_in[4];
    const float* Wv    = (const float*)d_in[5];
    const float* bv    = (const float*)d_in[6];
    const float* sigma = (const float*)d_in[7];
    const float* Wp1   = (const float*)d_in[8];
    const float* bp1   = (const float*)d_in[9];
    const float* Wp2   = (const float*)d_in[10];
    const float* bp2   = (const float*)d_in[11];
    const float* Wout  = (const float*)d_in[12];
    float* out = (float*)d_out;

    __half *qkv, *sc, *aw, *o, *wqkv, *wouth;
    float* bqkv;
    cudaGetSymbolAddress((void**)&qkv,   d_qkv);
    cudaGetSymbolAddress((void**)&sc,    d_sc);
    cudaGetSymbolAddress((void**)&aw,    d_aw);
    cudaGetSymbolAddress((void**)&o,     d_o);
    cudaGetSymbolAddress((void**)&wqkv,  d_wqkv);
    cudaGetSymbolAddress((void**)&wouth, d_wouth);
    cudaGetSymbolAddress((void**)&bqkv,  d_bqkv);

    const long S   = 512L * 512L;        // 262144
    const long SQ  = 512L * 2048L;       // per-batch qkv stride

    // 0. weight prepack (fp32 -> fp16)
    prepack<<<4096, 256>>>(Wq, Wk, Wv, bv, Wout);

    // 1. qkv = x @ [Wq|Wk|Wv] (+bias on v cols)   M=8192 N=2048 K=512
    gemm_h<0, 0, 1><<<dim3(64 * 32, 1), 256>>>(
        x, wqkv, qkv, bqkv,
        8192, 2048, 512, 512, 2048, 2048, 0, 0, 0, 0, 0, 0, 0);

    // 2. scores[b,g] = q_g @ k_g^T   (batch 128)  M=512 N=512 K=64
    gemm_h<1, 1, 1><<<dim3(4 * 8, 128), 256>>>(
        qkv, qkv + 512, sc, nullptr,
        512, 512, 64, 2048, 2048, 512,
        3, SQ, 64, SQ, 64, 8 * S, S);

    // 3. noise + MLP + prior + softmax(L)
    k_mid<<<16384, 256>>>(prior, eps, sigma, Wp1, bp1, Wp2, bp2);

    // 4. o[b,:,l,:] = aw[b,l] @ v[b,:,l,:]   (batch 256)  M=512 N=64 K=512
    gemm_h<1, 0, 1><<<dim3(4 * 1, 256), 256>>>(
        aw, qkv + 1024, o, nullptr,
        512, 64, 512, 512, 2048, 1024,
        4, 16 * S, S, SQ, 64, 512L * 1024L, 64);

    // 5. out = o @ Wout   M=8192 N=512 K=1024
    gemm_h<1, 0, 0><<<dim3(64 * 8, 1), 256>>>(
        o, wouth, out, nullptr,
        8192, 512, 1024, 1024, 512, 512, 0, 0, 0, 0, 0, 0, 0);
}